// round 1
// baseline (speedup 1.0000x reference)
#include <cuda_runtime.h>
#include <math.h>

#define B_ROWS    8192
#define DIM       768
#define NE        8
#define TPB       192              // 768 / 4 floats per thread
#define NWARP     (TPB / 32)

// Scratch for per-row sparse gates, expert-major for coalesced reduction.
// __device__ global array: allowed (no runtime allocation).
__device__ float g_gs_all[NE * B_ROWS];

__global__ __launch_bounds__(TPB)
void moe_gate_mix_kernel(const float* __restrict__ h,
                         const float* __restrict__ x,
                         const float* __restrict__ W,
                         const float* __restrict__ bias,
                         float* __restrict__ y)
{
    const int row  = blockIdx.x;
    const int t    = threadIdx.x;
    const int warp = t >> 5;
    const int lane = t & 31;

    __shared__ float s_red[NWARP][NE];
    __shared__ float s_gs[NE];

    // ---------- Stage 1: gate logits = x[row] @ W^T + b ----------
    const float4* x4 = reinterpret_cast<const float4*>(x + (size_t)row * DIM);
    const float4  xv = x4[t];                       // 4 consecutive d per thread

    float part[NE];
#pragma unroll
    for (int e = 0; e < NE; e++) {
        const float4* w4 = reinterpret_cast<const float4*>(W + e * DIM);
        const float4  wv = w4[t];                   // L2-resident after first wave
        part[e] = xv.x * wv.x + xv.y * wv.y + xv.z * wv.z + xv.w * wv.w;
    }

    // warp reduction of the 8 partials
#pragma unroll
    for (int e = 0; e < NE; e++) {
        float v = part[e];
#pragma unroll
        for (int o = 16; o > 0; o >>= 1)
            v += __shfl_xor_sync(0xffffffffu, v, o);
        part[e] = v;
    }
    if (lane == 0) {
#pragma unroll
        for (int e = 0; e < NE; e++) s_red[warp][e] = part[e];
    }
    __syncthreads();

    if (t == 0) {
        float lg[NE];
#pragma unroll
        for (int e = 0; e < NE; e++) {
            float v = bias[e];
#pragma unroll
            for (int w = 0; w < NWARP; w++) v += s_red[w][e];
            lg[e] = v;                               // TAU = 1.0
        }
        // dense softmax g (needed only for the log-correction term)
        float m = lg[0];
#pragma unroll
        for (int e = 1; e < NE; e++) m = fmaxf(m, lg[e]);
        float ex[NE], s = 0.f;
#pragma unroll
        for (int e = 0; e < NE; e++) { ex[e] = __expf(lg[e] - m); s += ex[e]; }
        const float inv_s = 1.f / s;

        // top-2 (ties vanishingly unlikely with continuous inputs; lower index wins)
        int i0 = 0;
#pragma unroll
        for (int e = 1; e < NE; e++) if (lg[e] > lg[i0]) i0 = e;
        int i1 = (i0 == 0) ? 1 : 0;
#pragma unroll
        for (int e = 0; e < NE; e++) if (e != i0 && lg[e] > lg[i1]) i1 = e;

        // adjusted logits and masked softmax over {i0, i1}
        const float g0 = ex[i0] * inv_s;
        const float g1 = ex[i1] * inv_s;
        const float a0 = lg[i0] - logf(fmaxf(2.f * (g0 + 1e-10f), 1e-10f));
        const float a1 = lg[i1] - logf(fmaxf(2.f * (g1 + 1e-10f), 1e-10f));
        const float am = fmaxf(a0, a1);
        const float e0 = expf(a0 - am);
        const float e1 = expf(a1 - am);
        const float ri = 1.f / (e0 + e1);

        float gs_loc[NE];
#pragma unroll
        for (int e = 0; e < NE; e++) gs_loc[e] = 0.f;
        gs_loc[i0] = e0 * ri;
        gs_loc[i1] = e1 * ri;
#pragma unroll
        for (int e = 0; e < NE; e++) {
            s_gs[e] = gs_loc[e];
            g_gs_all[e * B_ROWS + row] = gs_loc[e];
        }
    }
    __syncthreads();

    float gs[NE];
#pragma unroll
    for (int e = 0; e < NE; e++) gs[e] = s_gs[e];

    // ---------- Stage 2: y[row, d] = sum_e h[row, d, e] * gs[e] ----------
    // Thread t owns d in [4t, 4t+4): 8 consecutive float4 of h = 128B/thread.
    const float4* h4 = reinterpret_cast<const float4*>(h + (size_t)row * DIM * NE);
    float yv[4];
#pragma unroll
    for (int j = 0; j < 4; j++) {
        const int d = (t << 2) + j;
        const float4 a = h4[d * 2 + 0];
        const float4 c = h4[d * 2 + 1];
        yv[j] = a.x * gs[0] + a.y * gs[1] + a.z * gs[2] + a.w * gs[3]
              + c.x * gs[4] + c.y * gs[5] + c.z * gs[6] + c.w * gs[7];
    }
    float4* y4 = reinterpret_cast<float4*>(y + (size_t)row * DIM);
    y4[t] = make_float4(yv[0], yv[1], yv[2], yv[3]);
}

// Deterministic reduction: block e computes soft/hard means for expert e.
__global__ __launch_bounds__(256)
void moe_stats_kernel(float* __restrict__ stats_out)
{
    const int e = blockIdx.x;
    const int t = threadIdx.x;

    float ssoft = 0.f, shard = 0.f;
    for (int b = t; b < B_ROWS; b += 256) {
        const float v = g_gs_all[e * B_ROWS + b];
        ssoft += v;
        shard += (v < 1e-5f) ? 0.f : 1.f;   // 1 - s_concat
    }
    __shared__ float rs[256], rh[256];
    rs[t] = ssoft; rh[t] = shard;
    __syncthreads();
    for (int o = 128; o > 0; o >>= 1) {
        if (t < o) { rs[t] += rs[t + o]; rh[t] += rh[t + o]; }
        __syncthreads();
    }
    if (t == 0) {
        const float invB = 1.f / (float)B_ROWS;
        stats_out[e]      = rs[0] * invB;   // soft_averages
        stats_out[NE + e] = rh[0] * invB;   // hard_averages
    }
}

extern "C" void kernel_launch(void* const* d_in, const int* in_sizes, int n_in,
                              void* d_out, int out_size)
{
    const float* h    = (const float*)d_in[0];   // (8192, 768, 8)
    const float* x    = (const float*)d_in[1];   // (8192, 768)
    const float* W    = (const float*)d_in[2];   // (8, 768)
    const float* bias = (const float*)d_in[3];   // (8,)
    float* out = (float*)d_out;

    moe_gate_mix_kernel<<<B_ROWS, TPB>>>(h, x, W, bias, out);

    // stats appended after y (tuple concat: y, soft_averages, hard_averages)
    if (out_size >= (int)((size_t)B_ROWS * DIM + 2 * NE))
        moe_stats_kernel<<<NE, 256>>>(out + (size_t)B_ROWS * DIM);
}

// round 3
// speedup vs baseline: 1.5769x; 1.5769x over previous
#include <cuda_runtime.h>
#include <math.h>

#define B_ROWS    8192
#define DIM       768
#define NE        8
#define TPB       192              // 768 / 4 = 192 float4 per row of x
#define NWARP     (TPB / 32)

// Per-row sparse gates, expert-major for the coalesced stats reduction.
__device__ float g_gs_all[NE * B_ROWS];

__global__ __launch_bounds__(TPB)
void moe_gate_mix_kernel(const float* __restrict__ h,
                         const float* __restrict__ x,
                         const float* __restrict__ W,
                         const float* __restrict__ bias,
                         float* __restrict__ y)
{
    const int row  = blockIdx.x;
    const int t    = threadIdx.x;
    const int warp = t >> 5;
    const int lane = t & 31;

    __shared__ float s_red[NWARP][NE];
    __shared__ float s_gs[NE];

    // ---------- Issue ALL h loads first (latency overlaps the gate stage) ----
    // Thread t owns d = t + 192k (k=0..3): lanes are consecutive, so each
    // LDG.128 covers a contiguous 512B warp footprint (nL≈4-8, not 32).
    const float4* h4 = reinterpret_cast<const float4*>(h + (size_t)row * DIM * NE);
    float4 va[4], vb[4];
#pragma unroll
    for (int k = 0; k < 4; k++) {
        const int d = t + TPB * k;
        va[k] = h4[2 * d + 0];
        vb[k] = h4[2 * d + 1];
    }

    // ---------- Stage 1: gate logits = x[row] @ W^T + b ----------
    const float4* x4 = reinterpret_cast<const float4*>(x + (size_t)row * DIM);
    const float4  xv = x4[t];

    float part[NE];
#pragma unroll
    for (int e = 0; e < NE; e++) {
        const float4* w4 = reinterpret_cast<const float4*>(W + e * DIM);
        const float4  wv = w4[t];                  // 24KB total, L2/L1-resident
        part[e] = xv.x * wv.x + xv.y * wv.y + xv.z * wv.z + xv.w * wv.w;
    }
#pragma unroll
    for (int e = 0; e < NE; e++) {
        float v = part[e];
#pragma unroll
        for (int o = 16; o > 0; o >>= 1)
            v += __shfl_xor_sync(0xffffffffu, v, o);
        part[e] = v;
    }
    if (lane == 0) {
#pragma unroll
        for (int e = 0; e < NE; e++) s_red[warp][e] = part[e];
    }
    __syncthreads();

    if (t == 0) {
        float lg[NE];
#pragma unroll
        for (int e = 0; e < NE; e++) {
            float v = bias[e];
#pragma unroll
            for (int w = 0; w < NWARP; w++) v += s_red[w][e];
            lg[e] = v;                              // TAU = 1.0
        }
        float m = lg[0];
#pragma unroll
        for (int e = 1; e < NE; e++) m = fmaxf(m, lg[e]);
        float ex[NE], s = 0.f;
#pragma unroll
        for (int e = 0; e < NE; e++) { ex[e] = __expf(lg[e] - m); s += ex[e]; }
        const float inv_s = 1.f / s;

        int i0 = 0;
#pragma unroll
        for (int e = 1; e < NE; e++) if (lg[e] > lg[i0]) i0 = e;
        int i1 = (i0 == 0) ? 1 : 0;
#pragma unroll
        for (int e = 0; e < NE; e++) if (e != i0 && lg[e] > lg[i1]) i1 = e;

        const float g0 = ex[i0] * inv_s;
        const float g1 = ex[i1] * inv_s;
        const float a0 = lg[i0] - logf(fmaxf(2.f * (g0 + 1e-10f), 1e-10f));
        const float a1 = lg[i1] - logf(fmaxf(2.f * (g1 + 1e-10f), 1e-10f));
        const float am = fmaxf(a0, a1);
        const float e0 = expf(a0 - am);
        const float e1 = expf(a1 - am);
        const float ri = 1.f / (e0 + e1);

        float gs_loc[NE];
#pragma unroll
        for (int e = 0; e < NE; e++) gs_loc[e] = 0.f;
        gs_loc[i0] = e0 * ri;
        gs_loc[i1] = e1 * ri;
#pragma unroll
        for (int e = 0; e < NE; e++) {
            s_gs[e] = gs_loc[e];
            g_gs_all[e * B_ROWS + row] = gs_loc[e];
        }
    }
    __syncthreads();

    float gs[NE];
#pragma unroll
    for (int e = 0; e < NE; e++) gs[e] = s_gs[e];

    // ---------- Stage 2: y[row, d] = sum_e h[row, d, e] * gs[e] ----------
    float* yrow = y + (size_t)row * DIM;
#pragma unroll
    for (int k = 0; k < 4; k++) {
        const int d = t + TPB * k;
        const float4 a = va[k];
        const float4 c = vb[k];
        yrow[d] = a.x * gs[0] + a.y * gs[1] + a.z * gs[2] + a.w * gs[3]
                + c.x * gs[4] + c.y * gs[5] + c.z * gs[6] + c.w * gs[7];
    }
}

// Deterministic reduction: block e computes soft/hard means for expert e.
#define STPB 1024
__global__ __launch_bounds__(STPB)
void moe_stats_kernel(float* __restrict__ stats_out)
{
    const int e = blockIdx.x;
    const int t = threadIdx.x;

    float ssoft = 0.f, shard = 0.f;
#pragma unroll
    for (int b = t; b < B_ROWS; b += STPB) {
        const float v = g_gs_all[e * B_ROWS + b];
        ssoft += v;
        shard += (v < 1e-5f) ? 0.f : 1.f;          // 1 - s_concat
    }
    // warp reduce, then cross-warp via smem
    __shared__ float rs[STPB / 32], rh[STPB / 32];
#pragma unroll
    for (int o = 16; o > 0; o >>= 1) {
        ssoft += __shfl_xor_sync(0xffffffffu, ssoft, o);
        shard += __shfl_xor_sync(0xffffffffu, shard, o);
    }
    if ((t & 31) == 0) { rs[t >> 5] = ssoft; rh[t >> 5] = shard; }
    __syncthreads();
    if (t < 32) {
        float a = (t < STPB / 32) ? rs[t] : 0.f;
        float c = (t < STPB / 32) ? rh[t] : 0.f;
#pragma unroll
        for (int o = 16; o > 0; o >>= 1) {
            a += __shfl_xor_sync(0xffffffffu, a, o);
            c += __shfl_xor_sync(0xffffffffu, c, o);
        }
        if (t == 0) {
            const float invB = 1.f / (float)B_ROWS;
            stats_out[e]      = a * invB;          // soft_averages
            stats_out[NE + e] = c * invB;          // hard_averages
        }
    }
}

extern "C" void kernel_launch(void* const* d_in, const int* in_sizes, int n_in,
                              void* d_out, int out_size)
{
    const float* h    = (const float*)d_in[0];   // (8192, 768, 8)
    const float* x    = (const float*)d_in[1];   // (8192, 768)
    const float* W    = (const float*)d_in[2];   // (8, 768)
    const float* bias = (const float*)d_in[3];   // (8,)
    float* out = (float*)d_out;

    moe_gate_mix_kernel<<<B_ROWS, TPB>>>(h, x, W, bias, out);

    if (out_size >= (int)((size_t)B_ROWS * DIM + 2 * NE))
        moe_stats_kernel<<<NE, STPB>>>(out + (size_t)B_ROWS * DIM);
}